// round 1
// baseline (speedup 1.0000x reference)
#include <cuda_runtime.h>

#define N_ATOMS 100000
#define EDGES   400000
#define BGR     1024
#define FXD     78
#define DIM     32
#define OUTD    128
#define EMBD    128
#define VOCAB   26
#define NFLT    32
#define SEQ     1000
#define KW      8
#define CONVL   993           // SEQ - KW + 1
#define FLAT    31776         // NFLT * CONVL
#define COMB    2304          // 2*OUTD + 2*1024
#define H1DIM   1024
#define H2DIM   256
#define LMDIM   1024

// ------------------------- scratch (device globals) -------------------------
__device__ float g_p[N_ATOMS * DIM];        // per-node projection
__device__ float g_t[N_ATOMS * DIM];        // aggregated (p_i + sum p_j)
__device__ float g_y[N_ATOMS * DIM];        // MLP output, pre-BN
__device__ float g_stats[5 * 2 * DIM];      // per-layer BN sums / sumsq
__device__ float g_bn[2 * DIM];             // current-layer BN scale/shift
__device__ float g_xg[BGR * DIM];           // pooled graph features
__device__ float g_lut[KW * NFLT * VOCAB];  // conv LUT [k][f][v]
__device__ float g_A[(size_t)BGR * FLAT];   // conv activations (flattened)
__device__ float g_xtacc[BGR * OUTD];       // split-K accumulator for fc1_xt
__device__ float g_xc[BGR * COMB];          // concat buffer
__device__ float g_h1[BGR * H1DIM];
__device__ float g_h2acc[BGR * H2DIM];      // split-K accumulator for fc2
__device__ float g_h2[BGR * H2DIM];

// ------------------------------- zero scratch -------------------------------
__global__ void zero_kernel() {
    int idx = blockIdx.x * blockDim.x + threadIdx.x;
    int stride = gridDim.x * blockDim.x;
    for (int i = idx; i < BGR * OUTD; i += stride) g_xtacc[i] = 0.f;
    for (int i = idx; i < BGR * H2DIM; i += stride) g_h2acc[i] = 0.f;
    for (int i = idx; i < BGR * DIM; i += stride) g_xg[i] = 0.f;
    for (int i = idx; i < 5 * 2 * DIM; i += stride) g_stats[i] = 0.f;
}

// -------------------------- GIN: projection p = bn(h) @ Wa ------------------
// warp per node; lane j accumulates output column j. Also initializes t = p.
template <int FIN, bool HASBN>
__global__ void __launch_bounds__(256) proj_kernel(
    const float* __restrict__ hin, const float* __restrict__ wa,
    float* __restrict__ p, float* __restrict__ t)
{
    __shared__ float wa_s[FIN * DIM];
    __shared__ float bsc[DIM], bsh[DIM];
    int tid = threadIdx.x;
    for (int i = tid; i < FIN * DIM; i += blockDim.x) wa_s[i] = wa[i];
    if (HASBN && tid < DIM) { bsc[tid] = g_bn[tid]; bsh[tid] = g_bn[DIM + tid]; }
    __syncthreads();

    int lane = tid & 31;
    int node = blockIdx.x * (blockDim.x >> 5) + (tid >> 5);
    if (node >= N_ATOMS) return;

    const float* row = hin + (size_t)node * FIN;
    float acc = 0.f;
#pragma unroll 4
    for (int c = 0; c < FIN; c++) {
        float v = __ldg(row + c);
        if (HASBN) v = fmaf(v, bsc[c], bsh[c]);
        acc = fmaf(v, wa_s[c * DIM + lane], acc);
    }
    p[node * DIM + lane] = acc;
    t[node * DIM + lane] = acc;
}

// -------------------------- GIN: edge scatter t[dst] += p[src] --------------
__global__ void edge_kernel(const int* __restrict__ src, const int* __restrict__ dst,
                            const float* __restrict__ p, float* __restrict__ t)
{
    int idx = blockIdx.x * blockDim.x + threadIdx.x;
    int e = idx >> 5;
    if (e >= EDGES) return;
    int c = idx & 31;
    atomicAdd(&t[(size_t)dst[e] * DIM + c], p[(size_t)src[e] * DIM + c]);
}

// ----------- GIN: y = relu(relu(t+ba) @ Wb + bb), fused BN statistics -------
__global__ void __launch_bounds__(256) mlp2_kernel(
    const float* __restrict__ tin, const float* __restrict__ wb,
    const float* __restrict__ ba, const float* __restrict__ bb,
    float* __restrict__ y, float* __restrict__ stats)
{
    __shared__ float wb_s[DIM * DIM];
    int tid = threadIdx.x;
    for (int i = tid; i < DIM * DIM; i += blockDim.x) wb_s[i] = wb[i];
    __syncthreads();

    int lane = tid & 31;
    int warpId = blockIdx.x * (blockDim.x >> 5) + (tid >> 5);
    int nWarps = gridDim.x * (blockDim.x >> 5);
    float bav = ba[lane], bbv = bb[lane];
    float s0 = 0.f, s1 = 0.f;

    for (int i = warpId; i < N_ATOMS; i += nWarps) {
        float hidden = fmaxf(tin[i * DIM + lane] + bav, 0.f);
        float acc = bbv;
#pragma unroll
        for (int c = 0; c < DIM; c++) {
            float hv = __shfl_sync(0xffffffffu, hidden, c);
            acc = fmaf(hv, wb_s[c * DIM + lane], acc);
        }
        float yv = fmaxf(acc, 0.f);
        y[i * DIM + lane] = yv;
        s0 += yv;
        s1 += yv * yv;
    }
    atomicAdd(&stats[lane], s0);
    atomicAdd(&stats[DIM + lane], s1);
}

// --------------------------- GIN: BN finalize -------------------------------
__global__ void bnfin_kernel(const float* __restrict__ stats,
                             const float* __restrict__ gamma,
                             const float* __restrict__ beta)
{
    int c = threadIdx.x;
    float mu = stats[c] * (1.0f / N_ATOMS);
    float var = stats[DIM + c] * (1.0f / N_ATOMS) - mu * mu;
    float sc = gamma[c] * rsqrtf(var + 1e-5f);
    g_bn[c] = sc;
    g_bn[DIM + c] = beta[c] - mu * sc;
}

// ------------------------------ global add pool -----------------------------
__global__ void pool_kernel(const float* __restrict__ y, const int* __restrict__ batch,
                            float* __restrict__ xg)
{
    int idx = blockIdx.x * blockDim.x + threadIdx.x;
    if (idx >= N_ATOMS * DIM) return;
    int i = idx >> 5, c = idx & 31;
    float v = fmaf(y[idx], g_bn[c], g_bn[DIM + c]);
    atomicAdd(&xg[batch[i] * DIM + c], v);
}

// ---------------- fc1_xd: xc[:, 0:128] = relu(xg @ W + b) -------------------
__global__ void fc1xd_kernel(const float* __restrict__ xg, const float* __restrict__ w,
                             const float* __restrict__ bias, float* __restrict__ xc)
{
    int idx = blockIdx.x * blockDim.x + threadIdx.x;
    if (idx >= BGR * OUTD) return;
    int b = idx >> 7, o = idx & 127;
    float acc = bias[o];
#pragma unroll
    for (int c = 0; c < DIM; c++) acc = fmaf(xg[b * DIM + c], w[c * OUTD + o], acc);
    xc[(size_t)b * COMB + o] = fmaxf(acc, 0.f);
}

// ------------------------- conv LUT: M[k][f][v] ------------------------------
__global__ void lut_kernel(const float* __restrict__ emb, const float* __restrict__ w)
{
    int idx = blockIdx.x * blockDim.x + threadIdx.x;
    if (idx >= KW * NFLT * VOCAB) return;
    int v = idx % VOCAB;
    int f = (idx / VOCAB) % NFLT;
    int k = idx / (VOCAB * NFLT);
    float acc = 0.f;
#pragma unroll 4
    for (int c = 0; c < EMBD; c++)
        acc = fmaf(emb[v * EMBD + c], w[f * EMBD * KW + c * KW + k], acc);
    g_lut[idx] = acc;   // idx == (k*NFLT+f)*VOCAB + v
}

// --------------------- conv via LUT + relu, flattened -----------------------
__global__ void __launch_bounds__(256) conv_kernel(
    const int* __restrict__ target, const float* __restrict__ bias,
    float* __restrict__ A)
{
    __shared__ float lut_s[KW * NFLT * VOCAB];
    __shared__ int tok_s[SEQ];
    __shared__ float bias_s[NFLT];
    int b = blockIdx.x, tid = threadIdx.x;
    for (int i = tid; i < KW * NFLT * VOCAB; i += 256) lut_s[i] = g_lut[i];
    for (int i = tid; i < SEQ; i += 256) tok_s[i] = target[b * SEQ + i];
    if (tid < NFLT) bias_s[tid] = bias[tid];
    __syncthreads();

    for (int tpos = tid; tpos < CONVL; tpos += 256) {
        int tok[KW];
#pragma unroll
        for (int k = 0; k < KW; k++) tok[k] = tok_s[tpos + k];
#pragma unroll 4
        for (int f = 0; f < NFLT; f++) {
            float acc = bias_s[f];
#pragma unroll
            for (int k = 0; k < KW; k++)
                acc += lut_s[(k * NFLT + f) * VOCAB + tok[k]];
            A[(size_t)b * FLAT + f * CONVL + tpos] = fmaxf(acc, 0.f);
        }
    }
}

// -------------------------- generic tiled GEMM -------------------------------
// C[M,Nn] = A[M,K(lda)] @ W[K,Nn]; SPLIT: atomicAdd partials (no bias);
// else: C = relu(AW + bias).
#define BM 64
#define BN 64
#define BK 16

template <bool SPLIT>
__global__ void __launch_bounds__(256) gemm_kernel(
    const float* __restrict__ A, const float* __restrict__ W,
    float* __restrict__ C, const float* __restrict__ bias,
    int M, int Nn, int K, int lda, int ldc, int kchunk)
{
    __shared__ __align__(16) float As[BK][BM];
    __shared__ __align__(16) float Bs[BK][BN];
    int m0 = blockIdx.y * BM;
    int n0 = blockIdx.x * BN;
    int k0 = SPLIT ? blockIdx.z * kchunk : 0;
    int kend = SPLIT ? min(K, k0 + kchunk) : K;
    int tid = threadIdx.x;
    int arow = tid >> 2;            // 0..63
    int akv = (tid & 3) << 2;       // 0,4,8,12
    int brow = tid >> 4;            // 0..15
    int bnv = (tid & 15) << 2;      // 0..60
    int tx = tid & 15, ty = tid >> 4;
    float acc[4][4] = {};

    const float* Ap = A + (size_t)(m0 + arow) * lda + akv;
    const float* Wp = W + (size_t)brow * Nn + n0 + bnv;

    for (int k = k0; k < kend; k += BK) {
        float4 a = *(const float4*)(Ap + k);
        float4 bq = *(const float4*)(Wp + (size_t)k * Nn);
        As[akv + 0][arow] = a.x; As[akv + 1][arow] = a.y;
        As[akv + 2][arow] = a.z; As[akv + 3][arow] = a.w;
        *(float4*)&Bs[brow][bnv] = bq;
        __syncthreads();
#pragma unroll
        for (int kk = 0; kk < BK; kk++) {
            float4 av = *(const float4*)&As[kk][ty << 2];
            float4 bv = *(const float4*)&Bs[kk][tx << 2];
            acc[0][0] = fmaf(av.x, bv.x, acc[0][0]);
            acc[0][1] = fmaf(av.x, bv.y, acc[0][1]);
            acc[0][2] = fmaf(av.x, bv.z, acc[0][2]);
            acc[0][3] = fmaf(av.x, bv.w, acc[0][3]);
            acc[1][0] = fmaf(av.y, bv.x, acc[1][0]);
            acc[1][1] = fmaf(av.y, bv.y, acc[1][1]);
            acc[1][2] = fmaf(av.y, bv.z, acc[1][2]);
            acc[1][3] = fmaf(av.y, bv.w, acc[1][3]);
            acc[2][0] = fmaf(av.z, bv.x, acc[2][0]);
            acc[2][1] = fmaf(av.z, bv.y, acc[2][1]);
            acc[2][2] = fmaf(av.z, bv.z, acc[2][2]);
            acc[2][3] = fmaf(av.z, bv.w, acc[2][3]);
            acc[3][0] = fmaf(av.w, bv.x, acc[3][0]);
            acc[3][1] = fmaf(av.w, bv.y, acc[3][1]);
            acc[3][2] = fmaf(av.w, bv.z, acc[3][2]);
            acc[3][3] = fmaf(av.w, bv.w, acc[3][3]);
        }
        __syncthreads();
    }

#pragma unroll
    for (int i = 0; i < 4; i++) {
        int m = m0 + (ty << 2) + i;
#pragma unroll
        for (int j = 0; j < 4; j++) {
            int n = n0 + (tx << 2) + j;
            if (SPLIT) atomicAdd(&C[(size_t)m * ldc + n], acc[i][j]);
            else C[(size_t)m * ldc + n] = fmaxf(acc[i][j] + bias[n], 0.f);
        }
    }
}

// ---------------------- split-K epilogue: relu(acc + bias) ------------------
__global__ void epi_kernel(const float* __restrict__ acc, const float* __restrict__ bias,
                           float* __restrict__ dst, int rows, int cols,
                           int dstStride, int dstOff)
{
    int idx = blockIdx.x * blockDim.x + threadIdx.x;
    if (idx >= rows * cols) return;
    int r = idx / cols, c = idx - r * cols;
    dst[(size_t)r * dstStride + dstOff + c] = fmaxf(acc[idx] + bias[c], 0.f);
}

// --------------------------- LM copy into concat ----------------------------
__global__ void lmcopy_kernel(const float* __restrict__ drug, const float* __restrict__ prot,
                              float* __restrict__ xc)
{
    int idx = blockIdx.x * blockDim.x + threadIdx.x;
    if (idx >= BGR * 2 * LMDIM) return;
    int b = idx >> 11, j = idx & 2047;
    float v = (j < LMDIM) ? drug[b * LMDIM + j] : prot[b * LMDIM + (j - LMDIM)];
    xc[(size_t)b * COMB + 2 * OUTD + j] = v;
}

// --------------------------- final output layer -----------------------------
__global__ void out_kernel(const float* __restrict__ h2, const float* __restrict__ w,
                           const float* __restrict__ b, float* __restrict__ out)
{
    int tid = threadIdx.x;
    int lane = tid & 31;
    int row = blockIdx.x * (blockDim.x >> 5) + (tid >> 5);
    if (row >= BGR) return;
    float acc = 0.f;
#pragma unroll
    for (int k = 0; k < H2DIM / 32; k++)
        acc = fmaf(h2[row * H2DIM + k * 32 + lane], w[k * 32 + lane], acc);
#pragma unroll
    for (int off = 16; off; off >>= 1) acc += __shfl_xor_sync(0xffffffffu, acc, off);
    if (lane == 0) out[row] = acc + b[0];
}

// ================================ launcher ===================================
extern "C" void kernel_launch(void* const* d_in, const int* in_sizes, int n_in,
                              void* d_out, int out_size)
{
    (void)in_sizes; (void)n_in; (void)out_size;
    const float* x        = (const float*)d_in[0];
    const int*   ei       = (const int*)d_in[1];
    const int*   batch    = (const int*)d_in[2];
    const int*   target   = (const int*)d_in[3];
    const float* drug_lm  = (const float*)d_in[4];
    const float* prot_lm  = (const float*)d_in[5];
    const float* w1a      = (const float*)d_in[6];
    const float* b1a      = (const float*)d_in[7];
    const float* w1b      = (const float*)d_in[8];
    const float* b1b      = (const float*)d_in[9];
    const float* gw_a     = (const float*)d_in[10];
    const float* gb_a     = (const float*)d_in[11];
    const float* gw_b     = (const float*)d_in[12];
    const float* gb_b     = (const float*)d_in[13];
    const float* bn_gamma = (const float*)d_in[14];
    const float* bn_beta  = (const float*)d_in[15];
    const float* fc1_xd_w = (const float*)d_in[16];
    const float* fc1_xd_b = (const float*)d_in[17];
    const float* emb      = (const float*)d_in[18];
    const float* convxt_w = (const float*)d_in[19];
    const float* convxt_b = (const float*)d_in[20];
    const float* fc1_xt_w = (const float*)d_in[21];
    const float* fc1_xt_b = (const float*)d_in[22];
    const float* fc1_w    = (const float*)d_in[23];
    const float* fc1_b    = (const float*)d_in[24];
    const float* fc2_w    = (const float*)d_in[25];
    const float* fc2_b    = (const float*)d_in[26];
    const float* out_w    = (const float*)d_in[27];
    const float* out_b    = (const float*)d_in[28];
    float* out = (float*)d_out;

    const int* srcp = ei;
    const int* dstp = ei + EDGES;

    // resolve device-global scratch addresses (no allocation; capture-safe)
    void* vp;
    cudaGetSymbolAddress(&vp, g_p);      float* p_p      = (float*)vp;
    cudaGetSymbolAddress(&vp, g_t);      float* p_t      = (float*)vp;
    cudaGetSymbolAddress(&vp, g_y);      float* p_y      = (float*)vp;
    cudaGetSymbolAddress(&vp, g_stats);  float* p_stats  = (float*)vp;
    cudaGetSymbolAddress(&vp, g_xg);     float* p_xg     = (float*)vp;
    cudaGetSymbolAddress(&vp, g_A);      float* p_A      = (float*)vp;
    cudaGetSymbolAddress(&vp, g_xtacc);  float* p_xtacc  = (float*)vp;
    cudaGetSymbolAddress(&vp, g_xc);     float* p_xc     = (float*)vp;
    cudaGetSymbolAddress(&vp, g_h1);     float* p_h1     = (float*)vp;
    cudaGetSymbolAddress(&vp, g_h2acc);  float* p_h2acc  = (float*)vp;
    cudaGetSymbolAddress(&vp, g_h2);     float* p_h2     = (float*)vp;

    // 0) zero accumulators
    zero_kernel<<<512, 256>>>();

    // 1) protein branch: LUT -> conv activations -> fc1_xt (split-K GEMM)
    lut_kernel<<<(KW * NFLT * VOCAB + 255) / 256, 256>>>(emb, convxt_w);
    conv_kernel<<<BGR, 256>>>(target, convxt_b, p_A);
    {
        dim3 grid(OUTD / BN, BGR / BM, 16);
        gemm_kernel<true><<<grid, 256>>>(p_A, fc1_xt_w, p_xtacc, nullptr,
                                         BGR, OUTD, FLAT, FLAT, OUTD, 2000);
    }
    epi_kernel<<<(BGR * OUTD + 255) / 256, 256>>>(p_xtacc, fc1_xt_b, p_xc,
                                                  BGR, OUTD, COMB, OUTD);

    // 2) GIN layers
    for (int l = 0; l < 5; l++) {
        const float* wa = (l == 0) ? w1a : gw_a + (l - 1) * DIM * DIM;
        const float* ba = (l == 0) ? b1a : gb_a + (l - 1) * DIM;
        const float* wb = (l == 0) ? w1b : gw_b + (l - 1) * DIM * DIM;
        const float* bb = (l == 0) ? b1b : gb_b + (l - 1) * DIM;
        if (l == 0)
            proj_kernel<FXD, false><<<(N_ATOMS + 7) / 8, 256>>>(x, wa, p_p, p_t);
        else
            proj_kernel<DIM, true><<<(N_ATOMS + 7) / 8, 256>>>(p_y, wa, p_p, p_t);
        edge_kernel<<<(EDGES * 32) / 256, 256>>>(srcp, dstp, p_p, p_t);
        mlp2_kernel<<<512, 256>>>(p_t, wb, ba, bb, p_y, p_stats + l * 2 * DIM);
        bnfin_kernel<<<1, DIM>>>(p_stats + l * 2 * DIM, bn_gamma + l * DIM, bn_beta + l * DIM);
    }

    // 3) pool + fc1_xd + LM concat
    pool_kernel<<<(N_ATOMS * DIM) / 256, 256>>>(p_y, batch, p_xg);
    fc1xd_kernel<<<(BGR * OUTD + 255) / 256, 256>>>(p_xg, fc1_xd_w, fc1_xd_b, p_xc);
    lmcopy_kernel<<<(BGR * 2 * LMDIM) / 256, 256>>>(drug_lm, prot_lm, p_xc);

    // 4) head MLP
    {
        dim3 grid(H1DIM / BN, BGR / BM, 1);
        gemm_kernel<false><<<grid, 256>>>(p_xc, fc1_w, p_h1, fc1_b,
                                          BGR, H1DIM, COMB, COMB, H1DIM, 0);
    }
    {
        dim3 grid(H2DIM / BN, BGR / BM, 4);
        gemm_kernel<true><<<grid, 256>>>(p_h1, fc2_w, p_h2acc, nullptr,
                                         BGR, H2DIM, H1DIM, H1DIM, H2DIM, 256);
    }
    epi_kernel<<<(BGR * H2DIM + 255) / 256, 256>>>(p_h2acc, fc2_b, p_h2,
                                                   BGR, H2DIM, H2DIM, 0);
    out_kernel<<<BGR / 8, 256>>>(p_h2, out_w, out_b, out);
}

// round 3
// speedup vs baseline: 1.2917x; 1.2917x over previous
#include <cuda_runtime.h>
#include <cuda_fp16.h>
#include <cstdint>

#define N_ATOMS 100000
#define EDGES   400000
#define BGR     1024
#define FXD     78
#define DIM     32
#define OUTD    128
#define EMBD    128
#define VOCAB   26
#define NFLT    32
#define SEQ     1000
#define KW      8
#define CONVL   993           // SEQ - KW + 1
#define FLAT    31776         // NFLT * CONVL
#define COMB    2304          // 2*OUTD + 2*1024
#define H1DIM   1024
#define H2DIM   256
#define LMDIM   1024

// ------------------------- scratch (device globals) -------------------------
__device__ float g_p[N_ATOMS * DIM];
__device__ float g_t[N_ATOMS * DIM];
__device__ float g_y[N_ATOMS * DIM];
__device__ float g_stats[5 * 2 * DIM];
__device__ float g_bn[2 * DIM];
__device__ float g_xg[BGR * DIM];
__device__ float g_lut[KW * NFLT * VOCAB];

// fp16 hi/lo activation & weight buffers
__device__ __half g_Ah[(size_t)BGR * FLAT];
__device__ __half g_Al[(size_t)BGR * FLAT];
__device__ __half g_BxtH[(size_t)OUTD * FLAT];   // fc1_xt_w^T
__device__ __half g_BxtL[(size_t)OUTD * FLAT];
__device__ __half g_B1H[(size_t)H1DIM * COMB];   // fc1_w^T
__device__ __half g_B1L[(size_t)H1DIM * COMB];
__device__ __half g_B2H[(size_t)H2DIM * H1DIM];  // fc2_w^T
__device__ __half g_B2L[(size_t)H2DIM * H1DIM];
__device__ __half g_XCh[(size_t)BGR * COMB];
__device__ __half g_XCl[(size_t)BGR * COMB];
__device__ __half g_H1h[(size_t)BGR * H1DIM];
__device__ __half g_H1l[(size_t)BGR * H1DIM];

__device__ float g_xtacc[BGR * OUTD];
__device__ float g_h1acc[BGR * H1DIM];
__device__ float g_h2acc[BGR * H2DIM];
__device__ float g_h2[BGR * H2DIM];

__device__ __forceinline__ void split16(float v, __half& h, __half& l) {
    h = __float2half_rn(v);
    l = __float2half_rn(v - __half2float(h));
}

// ------------------------------- zero scratch -------------------------------
__global__ void zero_kernel() {
    int idx = blockIdx.x * blockDim.x + threadIdx.x;
    int stride = gridDim.x * blockDim.x;
    for (int i = idx; i < BGR * OUTD; i += stride) g_xtacc[i] = 0.f;
    for (int i = idx; i < BGR * H1DIM; i += stride) g_h1acc[i] = 0.f;
    for (int i = idx; i < BGR * H2DIM; i += stride) g_h2acc[i] = 0.f;
    for (int i = idx; i < BGR * DIM; i += stride) g_xg[i] = 0.f;
    for (int i = idx; i < 5 * 2 * DIM; i += stride) g_stats[i] = 0.f;
}

// -------------- weight transpose + fp16 split: W[K][N] -> Bt[N][K] ----------
__global__ void w16t_kernel(const float* __restrict__ W,
                            __half* __restrict__ Bh, __half* __restrict__ Bl,
                            int K, int N)
{
    __shared__ float ts[32][33];
    int k0 = blockIdx.x * 32, n0 = blockIdx.y * 32;
    int tx = threadIdx.x & 31, ty = threadIdx.x >> 5;   // 32 x 8
#pragma unroll
    for (int i = 0; i < 4; i++)
        ts[ty + i * 8][tx] = W[(size_t)(k0 + ty + i * 8) * N + n0 + tx];
    __syncthreads();
#pragma unroll
    for (int i = 0; i < 4; i++) {
        int n = ty + i * 8;
        float v = ts[tx][n];
        __half h, l; split16(v, h, l);
        size_t o = (size_t)(n0 + n) * K + k0 + tx;
        Bh[o] = h; Bl[o] = l;
    }
}

// =========================== fp16x3 MMA GEMM =================================
// C[M,N] += A @ B^T, with A=[M][K] (Ah+Al fp16), Bt=[N][K] (Bh+Bl fp16).
// CTA 128x128, BK=32, 8 warps of 32x64 tiles, split-K atomics into fp32 Cacc.
#define ASTR 40   // smem row stride in halfs (80B -> conflict-free ldmatrix)

__device__ __forceinline__ uint32_t smem_u32(const void* p) {
    uint32_t a;
    asm("{ .reg .u64 t; cvta.to.shared.u64 t, %1; cvt.u32.u64 %0, t; }"
        : "=r"(a) : "l"(p));
    return a;
}
__device__ __forceinline__ void ldm4(uint32_t* r, uint32_t saddr) {
    asm volatile("ldmatrix.sync.aligned.m8n8.x4.shared.b16 {%0,%1,%2,%3}, [%4];"
        : "=r"(r[0]), "=r"(r[1]), "=r"(r[2]), "=r"(r[3]) : "r"(saddr));
}
__device__ __forceinline__ void mma16816(float* d, const uint32_t* a,
                                         uint32_t b0, uint32_t b1) {
    asm volatile(
        "mma.sync.aligned.m16n8k16.row.col.f32.f16.f16.f32 "
        "{%0,%1,%2,%3}, {%4,%5,%6,%7}, {%8,%9}, {%0,%1,%2,%3};"
        : "+f"(d[0]), "+f"(d[1]), "+f"(d[2]), "+f"(d[3])
        : "r"(a[0]), "r"(a[1]), "r"(a[2]), "r"(a[3]), "r"(b0), "r"(b1));
}

__global__ void __launch_bounds__(256, 2) hgemm(
    const __half* __restrict__ Ah, const __half* __restrict__ Al,
    const __half* __restrict__ Bh, const __half* __restrict__ Bl,
    float* __restrict__ Cacc, int lda, int ldb, int ldc,
    int totalChunks, int chunksPerSplit)
{
    __shared__ __half sAh[128 * ASTR], sAl[128 * ASTR];
    __shared__ __half sBh[128 * ASTR], sBl[128 * ASTR];

    int tid = threadIdx.x, lane = tid & 31, wid = tid >> 5;
    int mw = wid & 3, nw = wid >> 2;
    int m0 = blockIdx.y * 128, n0 = blockIdx.x * 128;

    int c0 = blockIdx.z * chunksPerSplit;
    int c1 = min(totalChunks, c0 + chunksPerSplit);
    if (c0 >= c1) return;

    // gmem->smem: thread handles row r, 16-half segment q (two 16B vectors)
    int r = tid >> 1, q = (tid & 1) * 16;
    const __half* pAh = Ah + (size_t)(m0 + r) * lda + q;
    const __half* pAl = Al + (size_t)(m0 + r) * lda + q;
    const __half* pBh = Bh + (size_t)(n0 + r) * ldb + q;
    const __half* pBl = Bl + (size_t)(n0 + r) * ldb + q;
    __half* sAh_w = sAh + r * ASTR + q;
    __half* sAl_w = sAl + r * ASTR + q;
    __half* sBh_w = sBh + r * ASTR + q;
    __half* sBl_w = sBl + r * ASTR + q;

    // ldmatrix addresses
    uint32_t bAh = smem_u32(sAh), bAl = smem_u32(sAl);
    uint32_t bBh = smem_u32(sBh), bBl = smem_u32(sBl);
    int lrow = lane & 15, lcol = (lane >> 4) * 8;
    uint32_t ofsA[2], ofsB[4];
#pragma unroll
    for (int mt = 0; mt < 2; mt++)
        ofsA[mt] = ((mw * 32 + mt * 16 + lrow) * ASTR + lcol) * 2;
#pragma unroll
    for (int ng = 0; ng < 4; ng++)
        ofsB[ng] = ((nw * 64 + ng * 16 + lrow) * ASTR + lcol) * 2;

    float acc[2][8][4] = {};

    for (int c = c0; c < c1; c++) {
        size_t k0 = (size_t)c * 32;
        float4 v0, v1;
        v0 = *(const float4*)(pAh + k0); v1 = *(const float4*)(pAh + k0 + 8);
        *(float4*)sAh_w = v0; *(float4*)(sAh_w + 8) = v1;
        v0 = *(const float4*)(pAl + k0); v1 = *(const float4*)(pAl + k0 + 8);
        *(float4*)sAl_w = v0; *(float4*)(sAl_w + 8) = v1;
        v0 = *(const float4*)(pBh + k0); v1 = *(const float4*)(pBh + k0 + 8);
        *(float4*)sBh_w = v0; *(float4*)(sBh_w + 8) = v1;
        v0 = *(const float4*)(pBl + k0); v1 = *(const float4*)(pBl + k0 + 8);
        *(float4*)sBl_w = v0; *(float4*)(sBl_w + 8) = v1;
        __syncthreads();

#pragma unroll
        for (int ks = 0; ks < 2; ks++) {
            uint32_t ah[2][4], al[2][4];
            ldm4(ah[0], bAh + ofsA[0] + ks * 32);
            ldm4(ah[1], bAh + ofsA[1] + ks * 32);
            ldm4(al[0], bAl + ofsA[0] + ks * 32);
            ldm4(al[1], bAl + ofsA[1] + ks * 32);
#pragma unroll
            for (int ng = 0; ng < 4; ng++) {
                uint32_t bh[4], bl[4];
                ldm4(bh, bBh + ofsB[ng] + ks * 32);
                ldm4(bl, bBl + ofsB[ng] + ks * 32);
#pragma unroll
                for (int mt = 0; mt < 2; mt++) {
                    float* d0 = acc[mt][2 * ng];
                    float* d1 = acc[mt][2 * ng + 1];
                    mma16816(d0, ah[mt], bh[0], bh[2]);
                    mma16816(d0, ah[mt], bl[0], bl[2]);
                    mma16816(d0, al[mt], bh[0], bh[2]);
                    mma16816(d1, ah[mt], bh[1], bh[3]);
                    mma16816(d1, ah[mt], bl[1], bl[3]);
                    mma16816(d1, al[mt], bh[1], bh[3]);
                }
            }
        }
        __syncthreads();
    }

    // epilogue: split-K atomic accumulation
    int gid = lane >> 2, tig = lane & 3;
#pragma unroll
    for (int mt = 0; mt < 2; mt++) {
        int row = m0 + mw * 32 + mt * 16 + gid;
#pragma unroll
        for (int nt = 0; nt < 8; nt++) {
            int col = n0 + nw * 64 + nt * 8 + tig * 2;
            float* p0 = Cacc + (size_t)row * ldc + col;
            float* p1 = Cacc + (size_t)(row + 8) * ldc + col;
            atomicAdd(p0,     acc[mt][nt][0]);
            atomicAdd(p0 + 1, acc[mt][nt][1]);
            atomicAdd(p1,     acc[mt][nt][2]);
            atomicAdd(p1 + 1, acc[mt][nt][3]);
        }
    }
}

// -------------------------- GIN: projection p = bn(h) @ Wa ------------------
template <int FIN, bool HASBN>
__global__ void __launch_bounds__(256) proj_kernel(
    const float* __restrict__ hin, const float* __restrict__ wa,
    float* __restrict__ p, float* __restrict__ t)
{
    __shared__ float wa_s[FIN * DIM];
    __shared__ float bsc[DIM], bsh[DIM];
    int tid = threadIdx.x;
    for (int i = tid; i < FIN * DIM; i += blockDim.x) wa_s[i] = wa[i];
    if (HASBN && tid < DIM) { bsc[tid] = g_bn[tid]; bsh[tid] = g_bn[DIM + tid]; }
    __syncthreads();

    int lane = tid & 31;
    int node = blockIdx.x * (blockDim.x >> 5) + (tid >> 5);
    if (node >= N_ATOMS) return;

    const float* row = hin + (size_t)node * FIN;
    float acc = 0.f;
#pragma unroll 4
    for (int c = 0; c < FIN; c++) {
        float v = __ldg(row + c);
        if (HASBN) v = fmaf(v, bsc[c], bsh[c]);
        acc = fmaf(v, wa_s[c * DIM + lane], acc);
    }
    p[node * DIM + lane] = acc;
    t[node * DIM + lane] = acc;
}

// -------------------------- GIN: edge scatter t[dst] += p[src] --------------
__global__ void edge_kernel(const int* __restrict__ src, const int* __restrict__ dst,
                            const float* __restrict__ p, float* __restrict__ t)
{
    int idx = blockIdx.x * blockDim.x + threadIdx.x;
    int e = idx >> 5;
    if (e >= EDGES) return;
    int c = idx & 31;
    atomicAdd(&t[(size_t)dst[e] * DIM + c], p[(size_t)src[e] * DIM + c]);
}

// ----------- GIN: y = relu(relu(t+ba) @ Wb + bb), fused BN statistics -------
__global__ void __launch_bounds__(256) mlp2_kernel(
    const float* __restrict__ tin, const float* __restrict__ wb,
    const float* __restrict__ ba, const float* __restrict__ bb,
    float* __restrict__ y, float* __restrict__ stats)
{
    __shared__ float wb_s[DIM * DIM];
    int tid = threadIdx.x;
    for (int i = tid; i < DIM * DIM; i += blockDim.x) wb_s[i] = wb[i];
    __syncthreads();

    int lane = tid & 31;
    int warpId = blockIdx.x * (blockDim.x >> 5) + (tid >> 5);
    int nWarps = gridDim.x * (blockDim.x >> 5);
    float bav = ba[lane], bbv = bb[lane];
    float s0 = 0.f, s1 = 0.f;

    for (int i = warpId; i < N_ATOMS; i += nWarps) {
        float hidden = fmaxf(tin[i * DIM + lane] + bav, 0.f);
        float acc = bbv;
#pragma unroll
        for (int c = 0; c < DIM; c++) {
            float hv = __shfl_sync(0xffffffffu, hidden, c);
            acc = fmaf(hv, wb_s[c * DIM + lane], acc);
        }
        float yv = fmaxf(acc, 0.f);
        y[i * DIM + lane] = yv;
        s0 += yv;
        s1 += yv * yv;
    }
    atomicAdd(&stats[lane], s0);
    atomicAdd(&stats[DIM + lane], s1);
}

// --------------------------- GIN: BN finalize -------------------------------
__global__ void bnfin_kernel(const float* __restrict__ stats,
                             const float* __restrict__ gamma,
                             const float* __restrict__ beta)
{
    int c = threadIdx.x;
    float mu = stats[c] * (1.0f / N_ATOMS);
    float var = stats[DIM + c] * (1.0f / N_ATOMS) - mu * mu;
    float sc = gamma[c] * rsqrtf(var + 1e-5f);
    g_bn[c] = sc;
    g_bn[DIM + c] = beta[c] - mu * sc;
}

// ------------------------------ global add pool -----------------------------
__global__ void pool_kernel(const float* __restrict__ y, const int* __restrict__ batch,
                            float* __restrict__ xg)
{
    int idx = blockIdx.x * blockDim.x + threadIdx.x;
    if (idx >= N_ATOMS * DIM) return;
    int i = idx >> 5, c = idx & 31;
    float v = fmaf(y[idx], g_bn[c], g_bn[DIM + c]);
    atomicAdd(&xg[batch[i] * DIM + c], v);
}

// ---------- fc1_xd: xc[:, 0:128] = relu(xg @ W + b), fp16 split out ---------
__global__ void fc1xd_kernel(const float* __restrict__ xg, const float* __restrict__ w,
                             const float* __restrict__ bias)
{
    int idx = blockIdx.x * blockDim.x + threadIdx.x;
    if (idx >= BGR * OUTD) return;
    int b = idx >> 7, o = idx & 127;
    float acc = bias[o];
#pragma unroll
    for (int c = 0; c < DIM; c++) acc = fmaf(xg[b * DIM + c], w[c * OUTD + o], acc);
    float v = fmaxf(acc, 0.f);
    __half h, l; split16(v, h, l);
    size_t d = (size_t)b * COMB + o;
    g_XCh[d] = h; g_XCl[d] = l;
}

// ------------------------- conv LUT: M[k][f][v] ------------------------------
__global__ void lut_kernel(const float* __restrict__ emb, const float* __restrict__ w)
{
    int idx = blockIdx.x * blockDim.x + threadIdx.x;
    if (idx >= KW * NFLT * VOCAB) return;
    int v = idx % VOCAB;
    int f = (idx / VOCAB) % NFLT;
    int k = idx / (VOCAB * NFLT);
    float acc = 0.f;
#pragma unroll 4
    for (int c = 0; c < EMBD; c++)
        acc = fmaf(emb[v * EMBD + c], w[f * EMBD * KW + c * KW + k], acc);
    g_lut[idx] = acc;
}

// --------------- conv via LUT + relu, fp16 hi/lo flattened ------------------
__global__ void __launch_bounds__(256) conv_kernel(
    const int* __restrict__ target, const float* __restrict__ bias)
{
    __shared__ float lut_s[KW * NFLT * VOCAB];
    __shared__ int tok_s[SEQ];
    __shared__ float bias_s[NFLT];
    int b = blockIdx.x, tid = threadIdx.x;
    for (int i = tid; i < KW * NFLT * VOCAB; i += 256) lut_s[i] = g_lut[i];
    for (int i = tid; i < SEQ; i += 256) tok_s[i] = target[b * SEQ + i];
    if (tid < NFLT) bias_s[tid] = bias[tid];
    __syncthreads();

    for (int tpos = tid; tpos < CONVL; tpos += 256) {
        int tok[KW];
#pragma unroll
        for (int k = 0; k < KW; k++) tok[k] = tok_s[tpos + k];
#pragma unroll 4
        for (int f = 0; f < NFLT; f++) {
            float acc = bias_s[f];
#pragma unroll
            for (int k = 0; k < KW; k++)
                acc += lut_s[(k * NFLT + f) * VOCAB + tok[k]];
            float v = fmaxf(acc, 0.f);
            __half h, l; split16(v, h, l);
            size_t d = (size_t)b * FLAT + f * CONVL + tpos;
            g_Ah[d] = h; g_Al[d] = l;
        }
    }
}

// ------------- split-K epilogue: relu(acc+bias) -> fp16 hi/lo pair ----------
__global__ void epi16_kernel(const float* __restrict__ acc, const float* __restrict__ bias,
                             __half* __restrict__ Xh, __half* __restrict__ Xl,
                             int rows, int cols, int dstStride, int dstOff)
{
    int idx = blockIdx.x * blockDim.x + threadIdx.x;
    if (idx >= rows * cols) return;
    int r = idx / cols, c = idx - r * cols;
    float v = fmaxf(acc[idx] + bias[c], 0.f);
    __half h, l; split16(v, h, l);
    size_t d = (size_t)r * dstStride + dstOff + c;
    Xh[d] = h; Xl[d] = l;
}

// ---------------------- fp32 epilogue (h2) ----------------------------------
__global__ void epi_kernel(const float* __restrict__ acc, const float* __restrict__ bias,
                           float* __restrict__ dst, int rows, int cols)
{
    int idx = blockIdx.x * blockDim.x + threadIdx.x;
    if (idx >= rows * cols) return;
    int c = idx % cols;
    dst[idx] = fmaxf(acc[idx] + bias[c], 0.f);
}

// --------------------------- LM copy into concat (fp16) ---------------------
__global__ void lmcopy_kernel(const float* __restrict__ drug, const float* __restrict__ prot)
{
    int idx = blockIdx.x * blockDim.x + threadIdx.x;
    if (idx >= BGR * 2 * LMDIM) return;
    int b = idx >> 11, j = idx & 2047;
    float v = (j < LMDIM) ? drug[b * LMDIM + j] : prot[b * LMDIM + (j - LMDIM)];
    __half h, l; split16(v, h, l);
    size_t d = (size_t)b * COMB + 2 * OUTD + j;
    g_XCh[d] = h; g_XCl[d] = l;
}

// --------------------------- final output layer -----------------------------
__global__ void out_kernel(const float* __restrict__ h2, const float* __restrict__ w,
                           const float* __restrict__ b, float* __restrict__ out)
{
    int tid = threadIdx.x;
    int lane = tid & 31;
    int row = blockIdx.x * (blockDim.x >> 5) + (tid >> 5);
    if (row >= BGR) return;
    float acc = 0.f;
#pragma unroll
    for (int k = 0; k < H2DIM / 32; k++)
        acc = fmaf(h2[row * H2DIM + k * 32 + lane], w[k * 32 + lane], acc);
#pragma unroll
    for (int off = 16; off; off >>= 1) acc += __shfl_xor_sync(0xffffffffu, acc, off);
    if (lane == 0) out[row] = acc + b[0];
}

// ================================ launcher ===================================
extern "C" void kernel_launch(void* const* d_in, const int* in_sizes, int n_in,
                              void* d_out, int out_size)
{
    (void)in_sizes; (void)n_in; (void)out_size;
    const float* x        = (const float*)d_in[0];
    const int*   ei       = (const int*)d_in[1];
    const int*   batch    = (const int*)d_in[2];
    const int*   target   = (const int*)d_in[3];
    const float* drug_lm  = (const float*)d_in[4];
    const float* prot_lm  = (const float*)d_in[5];
    const float* w1a      = (const float*)d_in[6];
    const float* b1a      = (const float*)d_in[7];
    const float* w1b      = (const float*)d_in[8];
    const float* b1b      = (const float*)d_in[9];
    const float* gw_a     = (const float*)d_in[10];
    const float* gb_a     = (const float*)d_in[11];
    const float* gw_b     = (const float*)d_in[12];
    const float* gb_b     = (const float*)d_in[13];
    const float* bn_gamma = (const float*)d_in[14];
    const float* bn_beta  = (const float*)d_in[15];
    const float* fc1_xd_w = (const float*)d_in[16];
    const float* fc1_xd_b = (const float*)d_in[17];
    const float* emb      = (const float*)d_in[18];
    const float* convxt_w = (const float*)d_in[19];
    const float* convxt_b = (const float*)d_in[20];
    const float* fc1_xt_w = (const float*)d_in[21];
    const float* fc1_xt_b = (const float*)d_in[22];
    const float* fc1_w    = (const float*)d_in[23];
    const float* fc1_b    = (const float*)d_in[24];
    const float* fc2_w    = (const float*)d_in[25];
    const float* fc2_b    = (const float*)d_in[26];
    const float* out_w    = (const float*)d_in[27];
    const float* out_b    = (const float*)d_in[28];
    float* out = (float*)d_out;

    const int* srcp = ei;
    const int* dstp = ei + EDGES;

    void* vp;
    cudaGetSymbolAddress(&vp, g_p);      float* p_p     = (float*)vp;
    cudaGetSymbolAddress(&vp, g_t);      float* p_t     = (float*)vp;
    cudaGetSymbolAddress(&vp, g_y);      float* p_y     = (float*)vp;
    cudaGetSymbolAddress(&vp, g_stats);  float* p_stats = (float*)vp;
    cudaGetSymbolAddress(&vp, g_xg);     float* p_xg    = (float*)vp;
    cudaGetSymbolAddress(&vp, g_Ah);     __half* p_Ah   = (__half*)vp;
    cudaGetSymbolAddress(&vp, g_Al);     __half* p_Al   = (__half*)vp;
    cudaGetSymbolAddress(&vp, g_BxtH);   __half* p_BxtH = (__half*)vp;
    cudaGetSymbolAddress(&vp, g_BxtL);   __half* p_BxtL = (__half*)vp;
    cudaGetSymbolAddress(&vp, g_B1H);    __half* p_B1H  = (__half*)vp;
    cudaGetSymbolAddress(&vp, g_B1L);    __half* p_B1L  = (__half*)vp;
    cudaGetSymbolAddress(&vp, g_B2H);    __half* p_B2H  = (__half*)vp;
    cudaGetSymbolAddress(&vp, g_B2L);    __half* p_B2L  = (__half*)vp;
    cudaGetSymbolAddress(&vp, g_XCh);    __half* p_XCh  = (__half*)vp;
    cudaGetSymbolAddress(&vp, g_XCl);    __half* p_XCl  = (__half*)vp;
    cudaGetSymbolAddress(&vp, g_H1h);    __half* p_H1h  = (__half*)vp;
    cudaGetSymbolAddress(&vp, g_H1l);    __half* p_H1l  = (__half*)vp;
    cudaGetSymbolAddress(&vp, g_xtacc);  float* p_xtacc = (float*)vp;
    cudaGetSymbolAddress(&vp, g_h1acc);  float* p_h1acc = (float*)vp;
    cudaGetSymbolAddress(&vp, g_h2acc);  float* p_h2acc = (float*)vp;
    cudaGetSymbolAddress(&vp, g_h2);     float* p_h2    = (float*)vp;

    // 0) zero accumulators + weight conversions
    zero_kernel<<<512, 256>>>();
    { dim3 g(FLAT / 32, OUTD / 32);  w16t_kernel<<<g, 256>>>(fc1_xt_w, p_BxtH, p_BxtL, FLAT, OUTD); }
    { dim3 g(COMB / 32, H1DIM / 32); w16t_kernel<<<g, 256>>>(fc1_w, p_B1H, p_B1L, COMB, H1DIM); }
    { dim3 g(H1DIM / 32, H2DIM / 32); w16t_kernel<<<g, 256>>>(fc2_w, p_B2H, p_B2L, H1DIM, H2DIM); }

    // 1) protein branch: LUT -> conv (fp16 split) -> fc1_xt GEMM
    lut_kernel<<<(KW * NFLT * VOCAB + 255) / 256, 256>>>(emb, convxt_w);
    conv_kernel<<<BGR, 256>>>(target, convxt_b);
    {
        dim3 grid(OUTD / 128, BGR / 128, 48);   // (1, 8, 48)
        hgemm<<<grid, 256>>>(p_Ah, p_Al, p_BxtH, p_BxtL, p_xtacc,
                             FLAT, FLAT, OUTD, FLAT / 32, 21);
    }
    epi16_kernel<<<(BGR * OUTD + 255) / 256, 256>>>(p_xtacc, fc1_xt_b, p_XCh, p_XCl,
                                                    BGR, OUTD, COMB, OUTD);

    // 2) GIN layers
    for (int l = 0; l < 5; l++) {
        const float* wa = (l == 0) ? w1a : gw_a + (l - 1) * DIM * DIM;
        const float* ba = (l == 0) ? b1a : gb_a + (l - 1) * DIM;
        const float* wb = (l == 0) ? w1b : gw_b + (l - 1) * DIM * DIM;
        const float* bb = (l == 0) ? b1b : gb_b + (l - 1) * DIM;
        if (l == 0)
            proj_kernel<FXD, false><<<(N_ATOMS + 7) / 8, 256>>>(x, wa, p_p, p_t);
        else
            proj_kernel<DIM, true><<<(N_ATOMS + 7) / 8, 256>>>(p_y, wa, p_p, p_t);
        edge_kernel<<<(EDGES * 32) / 256, 256>>>(srcp, dstp, p_p, p_t);
        mlp2_kernel<<<512, 256>>>(p_t, wb, ba, bb, p_y, p_stats + l * 2 * DIM);
        bnfin_kernel<<<1, DIM>>>(p_stats + l * 2 * DIM, bn_gamma + l * DIM, bn_beta + l * DIM);
    }

    // 3) pool + fc1_xd + LM concat (all write fp16 xc)
    pool_kernel<<<(N_ATOMS * DIM) / 256, 256>>>(p_y, batch, p_xg);
    fc1xd_kernel<<<(BGR * OUTD + 255) / 256, 256>>>(p_xg, fc1_xd_w, fc1_xd_b);
    lmcopy_kernel<<<(BGR * 2 * LMDIM) / 256, 256>>>(drug_lm, prot_lm);

    // 4) head MLP: fc1 (split-K 6), fc2 (split-K 16), out
    {
        dim3 grid(H1DIM / 128, BGR / 128, 6);   // (8, 8, 6)
        hgemm<<<grid, 256>>>(p_XCh, p_XCl, p_B1H, p_B1L, p_h1acc,
                             COMB, COMB, H1DIM, COMB / 32, 12);
    }
    epi16_kernel<<<(BGR * H1DIM + 255) / 256, 256>>>(p_h1acc, fc1_b, p_H1h, p_H1l,
                                                     BGR, H1DIM, H1DIM, 0);
    {
        dim3 grid(H2DIM / 128, BGR / 128, 16);  // (2, 8, 16)
        hgemm<<<grid, 256>>>(p_H1h, p_H1l, p_B2H, p_B2L, p_h2acc,
                             H1DIM, H1DIM, H2DIM, H1DIM / 32, 2);
    }
    epi_kernel<<<(BGR * H2DIM + 255) / 256, 256>>>(p_h2acc, fc2_b, p_h2, BGR, H2DIM);
    out_kernel<<<BGR / 8, 256>>>(p_h2, out_w, out_b, out);
}

// round 4
// speedup vs baseline: 1.4720x; 1.1395x over previous
#include <cuda_runtime.h>
#include <cuda_fp16.h>
#include <cstdint>

#define N_ATOMS 100000
#define EDGES   400000
#define BGR     1024
#define FXD     78
#define DIM     32
#define OUTD    128
#define EMBD    128
#define VOCAB   26
#define NFLT    32
#define SEQ     1000
#define KW      8
#define CONVL   993           // SEQ - KW + 1
#define FLAT    31776         // NFLT * CONVL
#define COMB    2304          // 2*OUTD + 2*1024
#define H1DIM   1024
#define H2DIM   256
#define LMDIM   1024
#define NB_SCAN ((N_ATOMS + 255) / 256)   // 391

// ------------------------- scratch (device globals) -------------------------
__device__ float g_p[N_ATOMS * DIM];
__device__ float g_y[N_ATOMS * DIM];
__device__ float g_stats[5 * 2 * DIM];
__device__ float g_bn[2 * DIM];
__device__ float g_xg[BGR * DIM];
__device__ float g_lut[KW * NFLT * VOCAB];

// CSR scratch
__device__ int g_deg[N_ATOMS];
__device__ int g_rowptr[N_ATOMS + 1];
__device__ int g_cur[N_ATOMS];
__device__ int g_esorted[EDGES];
__device__ int g_blocksum[512];

// fp16 hi/lo activation & weight buffers
__device__ __half g_Ah[(size_t)BGR * FLAT];
__device__ __half g_Al[(size_t)BGR * FLAT];
__device__ __half g_BxtH[(size_t)OUTD * FLAT];   // fc1_xt_w^T
__device__ __half g_BxtL[(size_t)OUTD * FLAT];
__device__ __half g_B1H[(size_t)H1DIM * COMB];   // fc1_w^T
__device__ __half g_B1L[(size_t)H1DIM * COMB];
__device__ __half g_B2H[(size_t)H2DIM * H1DIM];  // fc2_w^T
__device__ __half g_B2L[(size_t)H2DIM * H1DIM];
__device__ __half g_XCh[(size_t)BGR * COMB];
__device__ __half g_XCl[(size_t)BGR * COMB];
__device__ __half g_H1h[(size_t)BGR * H1DIM];
__device__ __half g_H1l[(size_t)BGR * H1DIM];

__device__ float g_xtacc[BGR * OUTD];
__device__ float g_h1acc[BGR * H1DIM];
__device__ float g_h2acc[BGR * H2DIM];
__device__ float g_h2[BGR * H2DIM];

__device__ __forceinline__ void split16(float v, __half& h, __half& l) {
    h = __float2half_rn(v);
    l = __float2half_rn(v - __half2float(h));
}

// ------------------------------- zero scratch -------------------------------
__global__ void zero_kernel() {
    int idx = blockIdx.x * blockDim.x + threadIdx.x;
    int stride = gridDim.x * blockDim.x;
    for (int i = idx; i < BGR * OUTD; i += stride) g_xtacc[i] = 0.f;
    for (int i = idx; i < BGR * H1DIM; i += stride) g_h1acc[i] = 0.f;
    for (int i = idx; i < BGR * H2DIM; i += stride) g_h2acc[i] = 0.f;
    for (int i = idx; i < BGR * DIM; i += stride) g_xg[i] = 0.f;
    for (int i = idx; i < 5 * 2 * DIM; i += stride) g_stats[i] = 0.f;
    for (int i = idx; i < N_ATOMS; i += stride) g_deg[i] = 0;
}

// ----------------------------- CSR construction -----------------------------
__global__ void hist_kernel(const int* __restrict__ dst) {
    int e = blockIdx.x * blockDim.x + threadIdx.x;
    if (e < EDGES) atomicAdd(&g_deg[dst[e]], 1);
}

__global__ void scan1_kernel() {
    __shared__ int s[256];
    int tid = threadIdx.x;
    int i = blockIdx.x * 256 + tid;
    int v = (i < N_ATOMS) ? g_deg[i] : 0;
    s[tid] = v;
    __syncthreads();
#pragma unroll
    for (int o = 1; o < 256; o <<= 1) {
        int u = (tid >= o) ? s[tid - o] : 0;
        __syncthreads();
        s[tid] += u;
        __syncthreads();
    }
    if (i < N_ATOMS) g_rowptr[i] = s[tid] - v;   // exclusive within block
    if (tid == 255) g_blocksum[blockIdx.x] = s[255];
}

__global__ void scan2_kernel() {
    __shared__ int s[512];
    int tid = threadIdx.x;
    int v = (tid < NB_SCAN) ? g_blocksum[tid] : 0;
    s[tid] = v;
    __syncthreads();
#pragma unroll
    for (int o = 1; o < 512; o <<= 1) {
        int u = (tid >= o) ? s[tid - o] : 0;
        __syncthreads();
        s[tid] += u;
        __syncthreads();
    }
    if (tid < NB_SCAN) g_blocksum[tid] = s[tid] - v;  // exclusive
}

__global__ void scan3_kernel() {
    int i = blockIdx.x * blockDim.x + threadIdx.x;
    if (i < N_ATOMS) {
        int v = g_rowptr[i] + g_blocksum[i >> 8];
        g_rowptr[i] = v;
        g_cur[i] = v;
    }
    if (i == 0) g_rowptr[N_ATOMS] = EDGES;
}

__global__ void scatter_kernel(const int* __restrict__ src, const int* __restrict__ dst) {
    int e = blockIdx.x * blockDim.x + threadIdx.x;
    if (e >= EDGES) return;
    int pos = atomicAdd(&g_cur[dst[e]], 1);
    g_esorted[pos] = src[e];
}

// -------------- weight transpose + fp16 split: W[K][N] -> Bt[N][K] ----------
__global__ void w16t_kernel(const float* __restrict__ W,
                            __half* __restrict__ Bh, __half* __restrict__ Bl,
                            int K, int N)
{
    __shared__ float ts[32][33];
    int k0 = blockIdx.x * 32, n0 = blockIdx.y * 32;
    int tx = threadIdx.x & 31, ty = threadIdx.x >> 5;   // 32 x 8
#pragma unroll
    for (int i = 0; i < 4; i++)
        ts[ty + i * 8][tx] = W[(size_t)(k0 + ty + i * 8) * N + n0 + tx];
    __syncthreads();
#pragma unroll
    for (int i = 0; i < 4; i++) {
        int n = ty + i * 8;
        float v = ts[tx][n];
        __half h, l; split16(v, h, l);
        size_t o = (size_t)(n0 + n) * K + k0 + tx;
        Bh[o] = h; Bl[o] = l;
    }
}

// =========================== fp16x3 MMA GEMM =================================
#define ASTR 40   // smem row stride in halfs (80B -> conflict-free ldmatrix)

__device__ __forceinline__ uint32_t smem_u32(const void* p) {
    uint32_t a;
    asm("{ .reg .u64 t; cvta.to.shared.u64 t, %1; cvt.u32.u64 %0, t; }"
        : "=r"(a) : "l"(p));
    return a;
}
__device__ __forceinline__ void ldm4(uint32_t* r, uint32_t saddr) {
    asm volatile("ldmatrix.sync.aligned.m8n8.x4.shared.b16 {%0,%1,%2,%3}, [%4];"
        : "=r"(r[0]), "=r"(r[1]), "=r"(r[2]), "=r"(r[3]) : "r"(saddr));
}
__device__ __forceinline__ void mma16816(float* d, const uint32_t* a,
                                         uint32_t b0, uint32_t b1) {
    asm volatile(
        "mma.sync.aligned.m16n8k16.row.col.f32.f16.f16.f32 "
        "{%0,%1,%2,%3}, {%4,%5,%6,%7}, {%8,%9}, {%0,%1,%2,%3};"
        : "+f"(d[0]), "+f"(d[1]), "+f"(d[2]), "+f"(d[3])
        : "r"(a[0]), "r"(a[1]), "r"(a[2]), "r"(a[3]), "r"(b0), "r"(b1));
}

__global__ void __launch_bounds__(256, 2) hgemm(
    const __half* __restrict__ Ah, const __half* __restrict__ Al,
    const __half* __restrict__ Bh, const __half* __restrict__ Bl,
    float* __restrict__ Cacc, int lda, int ldb, int ldc,
    int totalChunks, int chunksPerSplit)
{
    __shared__ __half sAh[128 * ASTR], sAl[128 * ASTR];
    __shared__ __half sBh[128 * ASTR], sBl[128 * ASTR];

    int tid = threadIdx.x, lane = tid & 31, wid = tid >> 5;
    int mw = wid & 3, nw = wid >> 2;
    int m0 = blockIdx.y * 128, n0 = blockIdx.x * 128;

    int c0 = blockIdx.z * chunksPerSplit;
    int c1 = min(totalChunks, c0 + chunksPerSplit);
    if (c0 >= c1) return;

    int r = tid >> 1, q = (tid & 1) * 16;
    const __half* pAh = Ah + (size_t)(m0 + r) * lda + q;
    const __half* pAl = Al + (size_t)(m0 + r) * lda + q;
    const __half* pBh = Bh + (size_t)(n0 + r) * ldb + q;
    const __half* pBl = Bl + (size_t)(n0 + r) * ldb + q;
    __half* sAh_w = sAh + r * ASTR + q;
    __half* sAl_w = sAl + r * ASTR + q;
    __half* sBh_w = sBh + r * ASTR + q;
    __half* sBl_w = sBl + r * ASTR + q;

    uint32_t bAh = smem_u32(sAh), bAl = smem_u32(sAl);
    uint32_t bBh = smem_u32(sBh), bBl = smem_u32(sBl);
    int lrow = lane & 15, lcol = (lane >> 4) * 8;
    uint32_t ofsA[2], ofsB[4];
#pragma unroll
    for (int mt = 0; mt < 2; mt++)
        ofsA[mt] = ((mw * 32 + mt * 16 + lrow) * ASTR + lcol) * 2;
#pragma unroll
    for (int ng = 0; ng < 4; ng++)
        ofsB[ng] = ((nw * 64 + ng * 16 + lrow) * ASTR + lcol) * 2;

    float acc[2][8][4] = {};

    for (int c = c0; c < c1; c++) {
        size_t k0 = (size_t)c * 32;
        float4 v0, v1;
        v0 = *(const float4*)(pAh + k0); v1 = *(const float4*)(pAh + k0 + 8);
        *(float4*)sAh_w = v0; *(float4*)(sAh_w + 8) = v1;
        v0 = *(const float4*)(pAl + k0); v1 = *(const float4*)(pAl + k0 + 8);
        *(float4*)sAl_w = v0; *(float4*)(sAl_w + 8) = v1;
        v0 = *(const float4*)(pBh + k0); v1 = *(const float4*)(pBh + k0 + 8);
        *(float4*)sBh_w = v0; *(float4*)(sBh_w + 8) = v1;
        v0 = *(const float4*)(pBl + k0); v1 = *(const float4*)(pBl + k0 + 8);
        *(float4*)sBl_w = v0; *(float4*)(sBl_w + 8) = v1;
        __syncthreads();

#pragma unroll
        for (int ks = 0; ks < 2; ks++) {
            uint32_t ah[2][4], al[2][4];
            ldm4(ah[0], bAh + ofsA[0] + ks * 32);
            ldm4(ah[1], bAh + ofsA[1] + ks * 32);
            ldm4(al[0], bAl + ofsA[0] + ks * 32);
            ldm4(al[1], bAl + ofsA[1] + ks * 32);
#pragma unroll
            for (int ng = 0; ng < 4; ng++) {
                uint32_t bh[4], bl[4];
                ldm4(bh, bBh + ofsB[ng] + ks * 32);
                ldm4(bl, bBl + ofsB[ng] + ks * 32);
#pragma unroll
                for (int mt = 0; mt < 2; mt++) {
                    float* d0 = acc[mt][2 * ng];
                    float* d1 = acc[mt][2 * ng + 1];
                    mma16816(d0, ah[mt], bh[0], bh[2]);
                    mma16816(d0, ah[mt], bl[0], bl[2]);
                    mma16816(d0, al[mt], bh[0], bh[2]);
                    mma16816(d1, ah[mt], bh[1], bh[3]);
                    mma16816(d1, ah[mt], bl[1], bl[3]);
                    mma16816(d1, al[mt], bh[1], bh[3]);
                }
            }
        }
        __syncthreads();
    }

    int gid = lane >> 2, tig = lane & 3;
#pragma unroll
    for (int mt = 0; mt < 2; mt++) {
        int row = m0 + mw * 32 + mt * 16 + gid;
#pragma unroll
        for (int nt = 0; nt < 8; nt++) {
            int col = n0 + nw * 64 + nt * 8 + tig * 2;
            float* p0 = Cacc + (size_t)row * ldc + col;
            float* p1 = Cacc + (size_t)(row + 8) * ldc + col;
            atomicAdd(p0,     acc[mt][nt][0]);
            atomicAdd(p0 + 1, acc[mt][nt][1]);
            atomicAdd(p1,     acc[mt][nt][2]);
            atomicAdd(p1 + 1, acc[mt][nt][3]);
        }
    }
}

// -------------------------- GIN: projection p = bn(h) @ Wa ------------------
template <int FIN, bool HASBN>
__global__ void __launch_bounds__(256) proj_kernel(
    const float* __restrict__ hin, const float* __restrict__ wa,
    float* __restrict__ p)
{
    __shared__ float wa_s[FIN * DIM];
    __shared__ float bsc[DIM], bsh[DIM];
    int tid = threadIdx.x;
    for (int i = tid; i < FIN * DIM; i += blockDim.x) wa_s[i] = wa[i];
    if (HASBN && tid < DIM) { bsc[tid] = g_bn[tid]; bsh[tid] = g_bn[DIM + tid]; }
    __syncthreads();

    int lane = tid & 31;
    int node = blockIdx.x * (blockDim.x >> 5) + (tid >> 5);
    if (node >= N_ATOMS) return;

    const float* row = hin + (size_t)node * FIN;
    float acc = 0.f;
#pragma unroll 4
    for (int c = 0; c < FIN; c++) {
        float v = __ldg(row + c);
        if (HASBN) v = fmaf(v, bsc[c], bsh[c]);
        acc = fmaf(v, wa_s[c * DIM + lane], acc);
    }
    p[node * DIM + lane] = acc;
}

// ---- GIN fused: gather (CSR) + y = relu(relu(t+ba)@Wb + bb) + BN stats -----
__global__ void __launch_bounds__(256) mlp2agg_kernel(
    const float* __restrict__ p, const float* __restrict__ wb,
    const float* __restrict__ ba, const float* __restrict__ bb,
    float* __restrict__ y, float* __restrict__ stats)
{
    __shared__ float wb_s[DIM * DIM];
    int tid = threadIdx.x;
    for (int i = tid; i < DIM * DIM; i += blockDim.x) wb_s[i] = wb[i];
    __syncthreads();

    int lane = tid & 31;
    int warpId = blockIdx.x * (blockDim.x >> 5) + (tid >> 5);
    int nWarps = gridDim.x * (blockDim.x >> 5);
    float bav = ba[lane], bbv = bb[lane];
    float s0 = 0.f, s1 = 0.f;

    for (int i = warpId; i < N_ATOMS; i += nWarps) {
        int rr = (lane < 2) ? g_rowptr[i + lane] : 0;
        int r0 = __shfl_sync(0xffffffffu, rr, 0);
        int r1 = __shfl_sync(0xffffffffu, rr, 1);

        float t = p[(size_t)i * DIM + lane];
        for (int base = r0; base < r1; base += 32) {
            int myE = base + lane;
            int s = (myE < r1) ? g_esorted[myE] : 0;
            int cnt = min(r1 - base, 32);
            for (int j = 0; j < cnt; j++) {
                int sj = __shfl_sync(0xffffffffu, s, j);
                t += p[(size_t)sj * DIM + lane];
            }
        }

        float hidden = fmaxf(t + bav, 0.f);
        float acc = bbv;
#pragma unroll
        for (int c = 0; c < DIM; c++) {
            float hv = __shfl_sync(0xffffffffu, hidden, c);
            acc = fmaf(hv, wb_s[c * DIM + lane], acc);
        }
        float yv = fmaxf(acc, 0.f);
        y[(size_t)i * DIM + lane] = yv;
        s0 += yv;
        s1 += yv * yv;
    }
    atomicAdd(&stats[lane], s0);
    atomicAdd(&stats[DIM + lane], s1);
}

// --------------------------- GIN: BN finalize -------------------------------
__global__ void bnfin_kernel(const float* __restrict__ stats,
                             const float* __restrict__ gamma,
                             const float* __restrict__ beta)
{
    int c = threadIdx.x;
    float mu = stats[c] * (1.0f / N_ATOMS);
    float var = stats[DIM + c] * (1.0f / N_ATOMS) - mu * mu;
    float sc = gamma[c] * rsqrtf(var + 1e-5f);
    g_bn[c] = sc;
    g_bn[DIM + c] = beta[c] - mu * sc;
}

// ------------------------------ global add pool -----------------------------
__global__ void pool_kernel(const float* __restrict__ y, const int* __restrict__ batch,
                            float* __restrict__ xg)
{
    int idx = blockIdx.x * blockDim.x + threadIdx.x;
    if (idx >= N_ATOMS * DIM) return;
    int i = idx >> 5, c = idx & 31;
    float v = fmaf(y[idx], g_bn[c], g_bn[DIM + c]);
    atomicAdd(&xg[batch[i] * DIM + c], v);
}

// ---------- fc1_xd: xc[:, 0:128] = relu(xg @ W + b), fp16 split out ---------
__global__ void fc1xd_kernel(const float* __restrict__ xg, const float* __restrict__ w,
                             const float* __restrict__ bias)
{
    int idx = blockIdx.x * blockDim.x + threadIdx.x;
    if (idx >= BGR * OUTD) return;
    int b = idx >> 7, o = idx & 127;
    float acc = bias[o];
#pragma unroll
    for (int c = 0; c < DIM; c++) acc = fmaf(xg[b * DIM + c], w[c * OUTD + o], acc);
    float v = fmaxf(acc, 0.f);
    __half h, l; split16(v, h, l);
    size_t d = (size_t)b * COMB + o;
    g_XCh[d] = h; g_XCl[d] = l;
}

// ------------------------- conv LUT: M[k][f][v] ------------------------------
__global__ void lut_kernel(const float* __restrict__ emb, const float* __restrict__ w)
{
    int idx = blockIdx.x * blockDim.x + threadIdx.x;
    if (idx >= KW * NFLT * VOCAB) return;
    int v = idx % VOCAB;
    int f = (idx / VOCAB) % NFLT;
    int k = idx / (VOCAB * NFLT);
    float acc = 0.f;
#pragma unroll 4
    for (int c = 0; c < EMBD; c++)
        acc = fmaf(emb[v * EMBD + c], w[f * EMBD * KW + c * KW + k], acc);
    g_lut[idx] = acc;
}

// --------------- conv via LUT + relu, fp16 hi/lo flattened ------------------
__global__ void __launch_bounds__(256) conv_kernel(
    const int* __restrict__ target, const float* __restrict__ bias)
{
    __shared__ float lut_s[KW * NFLT * VOCAB];
    __shared__ int tok_s[SEQ];
    __shared__ float bias_s[NFLT];
    int b = blockIdx.x, tid = threadIdx.x;
    for (int i = tid; i < KW * NFLT * VOCAB; i += 256) lut_s[i] = g_lut[i];
    for (int i = tid; i < SEQ; i += 256) tok_s[i] = target[b * SEQ + i];
    if (tid < NFLT) bias_s[tid] = bias[tid];
    __syncthreads();

    for (int tpos = tid; tpos < CONVL; tpos += 256) {
        int tok[KW];
#pragma unroll
        for (int k = 0; k < KW; k++) tok[k] = tok_s[tpos + k];
#pragma unroll 4
        for (int f = 0; f < NFLT; f++) {
            float acc = bias_s[f];
#pragma unroll
            for (int k = 0; k < KW; k++)
                acc += lut_s[(k * NFLT + f) * VOCAB + tok[k]];
            float v = fmaxf(acc, 0.f);
            __half h, l; split16(v, h, l);
            size_t d = (size_t)b * FLAT + f * CONVL + tpos;
            g_Ah[d] = h; g_Al[d] = l;
        }
    }
}

// ------------- split-K epilogue: relu(acc+bias) -> fp16 hi/lo pair ----------
__global__ void epi16_kernel(const float* __restrict__ acc, const float* __restrict__ bias,
                             __half* __restrict__ Xh, __half* __restrict__ Xl,
                             int rows, int cols, int dstStride, int dstOff)
{
    int idx = blockIdx.x * blockDim.x + threadIdx.x;
    if (idx >= rows * cols) return;
    int r = idx / cols, c = idx - r * cols;
    float v = fmaxf(acc[idx] + bias[c], 0.f);
    __half h, l; split16(v, h, l);
    size_t d = (size_t)r * dstStride + dstOff + c;
    Xh[d] = h; Xl[d] = l;
}

// ---------------------- fp32 epilogue (h2) ----------------------------------
__global__ void epi_kernel(const float* __restrict__ acc, const float* __restrict__ bias,
                           float* __restrict__ dst, int rows, int cols)
{
    int idx = blockIdx.x * blockDim.x + threadIdx.x;
    if (idx >= rows * cols) return;
    int c = idx % cols;
    dst[idx] = fmaxf(acc[idx] + bias[c], 0.f);
}

// --------------------------- LM copy into concat (fp16) ---------------------
__global__ void lmcopy_kernel(const float* __restrict__ drug, const float* __restrict__ prot)
{
    int idx = blockIdx.x * blockDim.x + threadIdx.x;
    if (idx >= BGR * 2 * LMDIM) return;
    int b = idx >> 11, j = idx & 2047;
    float v = (j < LMDIM) ? drug[b * LMDIM + j] : prot[b * LMDIM + (j - LMDIM)];
    __half h, l; split16(v, h, l);
    size_t d = (size_t)b * COMB + 2 * OUTD + j;
    g_XCh[d] = h; g_XCl[d] = l;
}

// --------------------------- final output layer -----------------------------
__global__ void out_kernel(const float* __restrict__ h2, const float* __restrict__ w,
                           const float* __restrict__ b, float* __restrict__ out)
{
    int tid = threadIdx.x;
    int lane = tid & 31;
    int row = blockIdx.x * (blockDim.x >> 5) + (tid >> 5);
    if (row >= BGR) return;
    float acc = 0.f;
#pragma unroll
    for (int k = 0; k < H2DIM / 32; k++)
        acc = fmaf(h2[row * H2DIM + k * 32 + lane], w[k * 32 + lane], acc);
#pragma unroll
    for (int off = 16; off; off >>= 1) acc += __shfl_xor_sync(0xffffffffu, acc, off);
    if (lane == 0) out[row] = acc + b[0];
}

// ================================ launcher ===================================
extern "C" void kernel_launch(void* const* d_in, const int* in_sizes, int n_in,
                              void* d_out, int out_size)
{
    (void)in_sizes; (void)n_in; (void)out_size;
    const float* x        = (const float*)d_in[0];
    const int*   ei       = (const int*)d_in[1];
    const int*   batch    = (const int*)d_in[2];
    const int*   target   = (const int*)d_in[3];
    const float* drug_lm  = (const float*)d_in[4];
    const float* prot_lm  = (const float*)d_in[5];
    const float* w1a      = (const float*)d_in[6];
    const float* b1a      = (const float*)d_in[7];
    const float* w1b      = (const float*)d_in[8];
    const float* b1b      = (const float*)d_in[9];
    const float* gw_a     = (const float*)d_in[10];
    const float* gb_a     = (const float*)d_in[11];
    const float* gw_b     = (const float*)d_in[12];
    const float* gb_b     = (const float*)d_in[13];
    const float* bn_gamma = (const float*)d_in[14];
    const float* bn_beta  = (const float*)d_in[15];
    const float* fc1_xd_w = (const float*)d_in[16];
    const float* fc1_xd_b = (const float*)d_in[17];
    const float* emb      = (const float*)d_in[18];
    const float* convxt_w = (const float*)d_in[19];
    const float* convxt_b = (const float*)d_in[20];
    const float* fc1_xt_w = (const float*)d_in[21];
    const float* fc1_xt_b = (const float*)d_in[22];
    const float* fc1_w    = (const float*)d_in[23];
    const float* fc1_b    = (const float*)d_in[24];
    const float* fc2_w    = (const float*)d_in[25];
    const float* fc2_b    = (const float*)d_in[26];
    const float* out_w    = (const float*)d_in[27];
    const float* out_b    = (const float*)d_in[28];
    float* out = (float*)d_out;

    const int* srcp = ei;
    const int* dstp = ei + EDGES;

    void* vp;
    cudaGetSymbolAddress(&vp, g_p);      float* p_p     = (float*)vp;
    cudaGetSymbolAddress(&vp, g_y);      float* p_y     = (float*)vp;
    cudaGetSymbolAddress(&vp, g_stats);  float* p_stats = (float*)vp;
    cudaGetSymbolAddress(&vp, g_xg);     float* p_xg    = (float*)vp;
    cudaGetSymbolAddress(&vp, g_Ah);     __half* p_Ah   = (__half*)vp;
    cudaGetSymbolAddress(&vp, g_Al);     __half* p_Al   = (__half*)vp;
    cudaGetSymbolAddress(&vp, g_BxtH);   __half* p_BxtH = (__half*)vp;
    cudaGetSymbolAddress(&vp, g_BxtL);   __half* p_BxtL = (__half*)vp;
    cudaGetSymbolAddress(&vp, g_B1H);    __half* p_B1H  = (__half*)vp;
    cudaGetSymbolAddress(&vp, g_B1L);    __half* p_B1L  = (__half*)vp;
    cudaGetSymbolAddress(&vp, g_B2H);    __half* p_B2H  = (__half*)vp;
    cudaGetSymbolAddress(&vp, g_B2L);    __half* p_B2L  = (__half*)vp;
    cudaGetSymbolAddress(&vp, g_XCh);    __half* p_XCh  = (__half*)vp;
    cudaGetSymbolAddress(&vp, g_XCl);    __half* p_XCl  = (__half*)vp;
    cudaGetSymbolAddress(&vp, g_H1h);    __half* p_H1h  = (__half*)vp;
    cudaGetSymbolAddress(&vp, g_H1l);    __half* p_H1l  = (__half*)vp;
    cudaGetSymbolAddress(&vp, g_xtacc);  float* p_xtacc = (float*)vp;
    cudaGetSymbolAddress(&vp, g_h1acc);  float* p_h1acc = (float*)vp;
    cudaGetSymbolAddress(&vp, g_h2acc);  float* p_h2acc = (float*)vp;
    cudaGetSymbolAddress(&vp, g_h2);     float* p_h2    = (float*)vp;

    // 0) zero accumulators + CSR build + weight conversions
    zero_kernel<<<512, 256>>>();
    hist_kernel<<<(EDGES + 255) / 256, 256>>>(dstp);
    scan1_kernel<<<NB_SCAN, 256>>>();
    scan2_kernel<<<1, 512>>>();
    scan3_kernel<<<NB_SCAN, 256>>>();
    scatter_kernel<<<(EDGES + 255) / 256, 256>>>(srcp, dstp);

    { dim3 g(FLAT / 32, OUTD / 32);  w16t_kernel<<<g, 256>>>(fc1_xt_w, p_BxtH, p_BxtL, FLAT, OUTD); }
    { dim3 g(COMB / 32, H1DIM / 32); w16t_kernel<<<g, 256>>>(fc1_w, p_B1H, p_B1L, COMB, H1DIM); }
    { dim3 g(H1DIM / 32, H2DIM / 32); w16t_kernel<<<g, 256>>>(fc2_w, p_B2H, p_B2L, H1DIM, H2DIM); }

    // 1) protein branch: LUT -> conv (fp16 split) -> fc1_xt GEMM
    lut_kernel<<<(KW * NFLT * VOCAB + 255) / 256, 256>>>(emb, convxt_w);
    conv_kernel<<<BGR, 256>>>(target, convxt_b);
    {
        dim3 grid(OUTD / 128, BGR / 128, 37);   // 296 CTAs = one full wave @2/SM
        hgemm<<<grid, 256>>>(p_Ah, p_Al, p_BxtH, p_BxtL, p_xtacc,
                             FLAT, FLAT, OUTD, FLAT / 32, 27);
    }
    epi16_kernel<<<(BGR * OUTD + 255) / 256, 256>>>(p_xtacc, fc1_xt_b, p_XCh, p_XCl,
                                                    BGR, OUTD, COMB, OUTD);

    // 2) GIN layers (CSR gather, no atomics)
    for (int l = 0; l < 5; l++) {
        const float* wa = (l == 0) ? w1a : gw_a + (l - 1) * DIM * DIM;
        const float* ba = (l == 0) ? b1a : gb_a + (l - 1) * DIM;
        const float* wb = (l == 0) ? w1b : gw_b + (l - 1) * DIM * DIM;
        const float* bb = (l == 0) ? b1b : gb_b + (l - 1) * DIM;
        if (l == 0)
            proj_kernel<FXD, false><<<(N_ATOMS + 7) / 8, 256>>>(x, wa, p_p);
        else
            proj_kernel<DIM, true><<<(N_ATOMS + 7) / 8, 256>>>(p_y, wa, p_p);
        mlp2agg_kernel<<<512, 256>>>(p_p, wb, ba, bb, p_y, p_stats + l * 2 * DIM);
        bnfin_kernel<<<1, DIM>>>(p_stats + l * 2 * DIM, bn_gamma + l * DIM, bn_beta + l * DIM);
    }

    // 3) pool + fc1_xd + LM concat (all write fp16 xc)
    pool_kernel<<<(N_ATOMS * DIM) / 256, 256>>>(p_y, batch, p_xg);
    fc1xd_kernel<<<(BGR * OUTD + 255) / 256, 256>>>(p_xg, fc1_xd_w, fc1_xd_b);
    lmcopy_kernel<<<(BGR * 2 * LMDIM) / 256, 256>>>(drug_lm, prot_lm);

    // 4) head MLP: fc1 (split-K 4), fc2 (split-K 16), out
    {
        dim3 grid(H1DIM / 128, BGR / 128, 4);   // 256 CTAs, one wave
        hgemm<<<grid, 256>>>(p_XCh, p_XCl, p_B1H, p_B1L, p_h1acc,
                             COMB, COMB, H1DIM, COMB / 32, 18);
    }
    epi16_kernel<<<(BGR * H1DIM + 255) / 256, 256>>>(p_h1acc, fc1_b, p_H1h, p_H1l,
                                                     BGR, H1DIM, H1DIM, 0);
    {
        dim3 grid(H2DIM / 128, BGR / 128, 16);  // 256 CTAs, one wave
        hgemm<<<grid, 256>>>(p_H1h, p_H1l, p_B2H, p_B2L, p_h2acc,
                             H1DIM, H1DIM, H2DIM, H1DIM / 32, 2);
    }
    epi_kernel<<<(BGR * H2DIM + 255) / 256, 256>>>(p_h2acc, fc2_b, p_h2, BGR, H2DIM);
    out_kernel<<<BGR / 8, 256>>>(p_h2, out_w, out_b, out);
}